// round 6
// baseline (speedup 1.0000x reference)
#include <cuda_runtime.h>
#include <cstdint>

#define MAT 4096
#define SQ  1024
#define HD  128
#define NEG_BIG (-1e30f)

// Scratch (allocation-free rule: device globals)
__device__ float g_q  [(size_t)MAT * MAT];
__device__ float g_k  [(size_t)MAT * MAT];
__device__ float g_v  [(size_t)MAT * MAT];
__device__ float g_att[(size_t)MAT * MAT];   // k-permuted layout
__device__ float g_xr [(size_t)MAT * MAT];   // k-permuted + tf32-rounded
__device__ float g_wqr[(size_t)MAT * MAT];
__device__ float g_wkr[(size_t)MAT * MAT];
__device__ float g_wvr[(size_t)MAT * MAT];
__device__ float g_wor[(size_t)MAT * MAT];

// ---------------------------------------------------------------------------
__device__ __forceinline__ float tf32r(float x) {
    uint32_t u;
    asm("cvt.rna.tf32.f32 %0, %1;" : "=r"(u) : "f"(x));
    return __uint_as_float(u);
}

__device__ __forceinline__ uint32_t smem_u32(const void* p) {
    uint32_t a;
    asm("{ .reg .u64 t; cvta.to.shared.u64 t, %1; cvt.u32.u64 %0, t; }" : "=r"(a) : "l"(p));
    return a;
}

__device__ __forceinline__ void mma8(float c[4], const uint32_t a[4], const uint32_t b[2]) {
    asm volatile(
        "mma.sync.aligned.m16n8k8.row.col.f32.tf32.tf32.f32 "
        "{%0,%1,%2,%3},{%4,%5,%6,%7},{%8,%9},{%0,%1,%2,%3};\n"
        : "+f"(c[0]), "+f"(c[1]), "+f"(c[2]), "+f"(c[3])
        : "r"(a[0]), "r"(a[1]), "r"(a[2]), "r"(a[3]), "r"(b[0]), "r"(b[1]));
}

__device__ __forceinline__ void cpa16(uint32_t dst, const void* src) {
    asm volatile("cp.async.cg.shared.global [%0], [%1], 16;" :: "r"(dst), "l"(src));
}
#define CPA_COMMIT() asm volatile("cp.async.commit_group;" ::: "memory")
#define CPA_WAIT(n)  asm volatile("cp.async.wait_group %0;" :: "n"(n) : "memory")

// ---------------------------------------------------------------------------
// tf32 round + k-permute pre-pass.
// Within every 8-float k-block: out[2*(k%4) + k/4] = tf32(in[k]).
// Shared by both GEMM operands -> dot products unchanged.
// Each thread handles one 8-block as two float4 loads / two float4 stores.
// ---------------------------------------------------------------------------
__global__ void round_perm_k(const float4* __restrict__ in, float4* __restrict__ out, int n8) {
    int i = blockIdx.x * blockDim.x + threadIdx.x;
    int stride = gridDim.x * blockDim.x;
    for (; i < n8; i += stride) {
        float4 lo = in[2 * i];
        float4 hi = in[2 * i + 1];
        float4 o0 = make_float4(tf32r(lo.x), tf32r(hi.x), tf32r(lo.y), tf32r(hi.y));
        float4 o1 = make_float4(tf32r(lo.z), tf32r(hi.z), tf32r(lo.w), tf32r(hi.w));
        out[2 * i]     = o0;
        out[2 * i + 1] = o1;
    }
}

// ---------------------------------------------------------------------------
// GEMM: C[m][n] = sum_k A[m][k] * W[n][k]  (4096^3), inputs tf32 + k-permuted.
// CTA 128x128, BK=32, 8 warps (warp tile 32x64), 2-stage cp.async pipeline.
// SSTR=40 -> conflict-free LDS.64 fragment loads; 81.9KB smem -> 2 CTAs/SM.
// ---------------------------------------------------------------------------
#define BM 128
#define BN 128
#define BK 32
#define SSTR 40
#define ABUF (BM * SSTR)                  // 5120 floats
#define BBUF (BN * SSTR)
#define SPF  (ABUF + BBUF)                // 10240 floats / stage
#define NSTG 2
#define GS   (NSTG * SPF * 4)             // 81920 B
#define NKT  (MAT / BK)                   // 128

__global__ __launch_bounds__(256, 2) void gemm_simt(
    const float* __restrict__ A, const float* __restrict__ W, float* __restrict__ C,
    const float* __restrict__ cosT, const float* __restrict__ sinT, int doRope)
{
    extern __shared__ float sm[];
    const uint32_t smb = smem_u32(sm);

    const int tid = threadIdx.x;
    const int bn = blockIdx.x, bm = blockIdx.y;

    const float* Abase = A + (size_t)(bm * BM) * MAT;
    const float* Wbase = W + (size_t)(bn * BN) * MAT;

    auto issue = [&](int i) {
        const uint32_t as = smb + (uint32_t)((i & 1) * SPF) * 4u;
        const uint32_t bs = as + ABUF * 4u;
        const int kb = i * BK;
#pragma unroll
        for (int j = 0; j < 4; j++) {          // A: 1024 16B-chunks
            const int idx = tid + j * 256;
            const int r = idx >> 3, cc = (idx & 7) << 2;
            cpa16(as + (uint32_t)(r * SSTR + cc) * 4u,
                  Abase + (size_t)r * MAT + kb + cc);
        }
#pragma unroll
        for (int j = 0; j < 4; j++) {          // B: 1024 16B-chunks
            const int idx = tid + j * 256;
            const int r = idx >> 3, cc = (idx & 7) << 2;
            cpa16(bs + (uint32_t)(r * SSTR + cc) * 4u,
                  Wbase + (size_t)r * MAT + kb + cc);
        }
        CPA_COMMIT();
    };

    issue(0);
    issue(1);

    const int lane = tid & 31, wrp = tid >> 5;
    const int g = lane >> 2, t = lane & 3;
    const int m0 = (wrp & 3) * 32;            // 4 M-slots
    const int n0 = (wrp >> 2) * 64;           // 2 N-slots

    float acc[2][8][4];
#pragma unroll
    for (int a = 0; a < 2; a++)
#pragma unroll
        for (int b = 0; b < 8; b++)
#pragma unroll
            for (int c = 0; c < 4; c++) acc[a][b][c] = 0.f;

    for (int kt = 0; kt < NKT; kt++) {
        CPA_WAIT(1);
        __syncthreads();

        // fragment base pointers in 8B units (k-permuted layout -> LDS.64)
        const uint2* s2 = reinterpret_cast<const uint2*>(sm + (kt & 1) * SPF);
        const uint2* a2 = s2;
        const uint2* b2 = s2 + ABUF / 2;

#pragma unroll
        for (int ks = 0; ks < 4; ks++) {
            const int kk = ks * 4 + t;        // (k0 + 2t)/2
            uint32_t af[2][4];
#pragma unroll
            for (int mt = 0; mt < 2; mt++) {
                const int r = m0 + mt * 16 + g;
                const uint2 lo = a2[r * (SSTR / 2) + kk];          // (a0, a2)
                const uint2 hi = a2[(r + 8) * (SSTR / 2) + kk];    // (a1, a3)
                af[mt][0] = lo.x; af[mt][1] = hi.x; af[mt][2] = lo.y; af[mt][3] = hi.y;
            }
#pragma unroll
            for (int nt = 0; nt < 8; nt++) {
                const int n = n0 + nt * 8 + g;
                const uint2 bb = b2[n * (SSTR / 2) + kk];          // (b0, b1)
                uint32_t bf[2] = { bb.x, bb.y };
                mma8(acc[0][nt], af[0], bf);
                mma8(acc[1][nt], af[1], bf);
            }
        }

        if (kt + 2 < NKT) {
            __syncthreads();                   // all reads of buffer (kt&1) done
            issue(kt + 2);
        }
    }

    // epilogue (+ fused RoPE); output layout is NOT permuted
#pragma unroll
    for (int mt = 0; mt < 2; mt++) {
        const int gm = bm * BM + m0 + mt * 16 + g;
        const int s0 = gm & (SQ - 1);
#pragma unroll
        for (int nt = 0; nt < 8; nt++) {
            const int cloc = n0 + nt * 8 + 2 * t;       // < 128
            const int gn = bn * BN + cloc;
            float v0 = acc[mt][nt][0], v1 = acc[mt][nt][1];
            float v2 = acc[mt][nt][2], v3 = acc[mt][nt][3];
            if (doRope) {
                const int p = cloc >> 1;                // pair index within head
                const float cc0 = cosT[s0 * 64 + p],       ss0 = sinT[s0 * 64 + p];
                const float cc1 = cosT[(s0 + 8) * 64 + p], ss1 = sinT[(s0 + 8) * 64 + p];
                const float w0 = v0 * cc0 - v1 * ss0;
                const float w1 = v0 * ss0 + v1 * cc0;
                const float w2 = v2 * cc1 - v3 * ss1;
                const float w3 = v2 * ss1 + v3 * cc1;
                v0 = w0; v1 = w1; v2 = w2; v3 = w3;
            }
            *reinterpret_cast<float2*>(C + (size_t)gm * MAT + gn)       = make_float2(v0, v1);
            *reinterpret_cast<float2*>(C + (size_t)(gm + 8) * MAT + gn) = make_float2(v2, v3);
        }
    }
}

// ---------------------------------------------------------------------------
// Flash attention. Math unchanged; the OUTPUT store applies the k-permutation
// (within each 8-col block) + tf32 rounding so the Wo GEMM can consume it
// directly in permuted layout.
// ---------------------------------------------------------------------------
#define QSTR 132
#define KSTR 132
#define VSTR 136
#define PSTR 68

__global__ __launch_bounds__(256, 1) void attn128(
    const float* __restrict__ Q, const float* __restrict__ K,
    const float* __restrict__ V, float* __restrict__ O)
{
    extern __shared__ float sm[];
    float* Qs = sm;
    float* Ks = Qs + 128 * QSTR;
    float* Vs = Ks + 64 * KSTR;
    float* Ps = Vs + 64 * VSTR;

    const int tid = threadIdx.x;
    const int qt = blockIdx.x, h = blockIdx.y, b = blockIdx.z;
    const int qbase = qt * 128;
    const size_t rowbase = (size_t)b * SQ;
    const float scale = 0.08838834764831845f;

    {
        const float* qp = Q + (rowbase + qbase) * MAT + h * HD;
#pragma unroll
        for (int i = 0; i < 16; i++) {
            int idx = tid + i * 256;
            int row = idx >> 5;
            int c4  = (idx & 31) << 2;
            float4 v = *reinterpret_cast<const float4*>(qp + (size_t)row * MAT + c4);
            v.x = tf32r(v.x * scale); v.y = tf32r(v.y * scale);
            v.z = tf32r(v.z * scale); v.w = tf32r(v.w * scale);
            *reinterpret_cast<float4*>(Qs + row * QSTR + c4) = v;
        }
    }

    const int lane = tid & 31, wrp = tid >> 5;
    const int g = lane >> 2, t = lane & 3;
    const int r0 = wrp * 16;

    float o[16][4];
#pragma unroll
    for (int i = 0; i < 16; i++)
#pragma unroll
        for (int j = 0; j < 4; j++) o[i][j] = 0.f;
    float m0 = NEG_BIG, m1 = NEG_BIG, l0 = 0.f, l1 = 0.f;

    const int nkt = 2 * qt + 2;
    for (int kt = 0; kt < nkt; kt++) {
        __syncthreads();
        {
            const float* kp = K + (rowbase + kt * 64) * MAT + h * HD;
            const float* vp = V + (rowbase + kt * 64) * MAT + h * HD;
#pragma unroll
            for (int i = 0; i < 8; i++) {
                int idx = tid + i * 256;
                int row = idx >> 5;
                int c4  = (idx & 31) << 2;
                float4 kv = *reinterpret_cast<const float4*>(kp + (size_t)row * MAT + c4);
                kv.x = tf32r(kv.x); kv.y = tf32r(kv.y); kv.z = tf32r(kv.z); kv.w = tf32r(kv.w);
                *reinterpret_cast<float4*>(Ks + row * KSTR + c4) = kv;
                float4 vv = *reinterpret_cast<const float4*>(vp + (size_t)row * MAT + c4);
                vv.x = tf32r(vv.x); vv.y = tf32r(vv.y); vv.z = tf32r(vv.z); vv.w = tf32r(vv.w);
                *reinterpret_cast<float4*>(Vs + row * VSTR + c4) = vv;
            }
        }
        __syncthreads();

        float sfr[8][4];
#pragma unroll
        for (int i = 0; i < 8; i++)
#pragma unroll
            for (int j = 0; j < 4; j++) sfr[i][j] = 0.f;

        const uint32_t* qsu = reinterpret_cast<const uint32_t*>(Qs);
        const uint32_t* ksu = reinterpret_cast<const uint32_t*>(Ks);
#pragma unroll
        for (int ks = 0; ks < 16; ks++) {
            const int k0 = ks * 8;
            uint32_t af[4] = {
                qsu[(r0 + g) * QSTR + k0 + t],
                qsu[(r0 + g + 8) * QSTR + k0 + t],
                qsu[(r0 + g) * QSTR + k0 + t + 4],
                qsu[(r0 + g + 8) * QSTR + k0 + t + 4] };
#pragma unroll
            for (int nt = 0; nt < 8; nt++) {
                uint32_t bf[2] = { ksu[(nt * 8 + g) * KSTR + k0 + t],
                                   ksu[(nt * 8 + g) * KSTR + k0 + t + 4] };
                mma8(sfr[nt], af, bf);
            }
        }

        if (kt >= 2 * qt) {
            const int qg0 = qbase + r0 + g;
            const int qg1 = qg0 + 8;
#pragma unroll
            for (int nt = 0; nt < 8; nt++) {
                const int kg = kt * 64 + nt * 8 + 2 * t;
                if (kg     > qg0) sfr[nt][0] = NEG_BIG;
                if (kg + 1 > qg0) sfr[nt][1] = NEG_BIG;
                if (kg     > qg1) sfr[nt][2] = NEG_BIG;
                if (kg + 1 > qg1) sfr[nt][3] = NEG_BIG;
            }
        }

        float tm0 = NEG_BIG, tm1 = NEG_BIG;
#pragma unroll
        for (int nt = 0; nt < 8; nt++) {
            tm0 = fmaxf(tm0, fmaxf(sfr[nt][0], sfr[nt][1]));
            tm1 = fmaxf(tm1, fmaxf(sfr[nt][2], sfr[nt][3]));
        }
        tm0 = fmaxf(tm0, __shfl_xor_sync(0xffffffffu, tm0, 1));
        tm0 = fmaxf(tm0, __shfl_xor_sync(0xffffffffu, tm0, 2));
        tm1 = fmaxf(tm1, __shfl_xor_sync(0xffffffffu, tm1, 1));
        tm1 = fmaxf(tm1, __shfl_xor_sync(0xffffffffu, tm1, 2));

        const float mn0 = fmaxf(m0, tm0), mn1 = fmaxf(m1, tm1);
        const float a0 = __expf(m0 - mn0), a1 = __expf(m1 - mn1);
        float ls0 = 0.f, ls1 = 0.f;
        float* Pw = Ps + wrp * 16 * PSTR;
#pragma unroll
        for (int nt = 0; nt < 8; nt++) {
            const int col = nt * 8 + 2 * t;
            float p0 = __expf(sfr[nt][0] - mn0);
            float p1 = __expf(sfr[nt][1] - mn0);
            float p2 = __expf(sfr[nt][2] - mn1);
            float p3 = __expf(sfr[nt][3] - mn1);
            ls0 += p0 + p1; ls1 += p2 + p3;
            Pw[g * PSTR + col]           = tf32r(p0);
            Pw[g * PSTR + col + 1]       = tf32r(p1);
            Pw[(g + 8) * PSTR + col]     = tf32r(p2);
            Pw[(g + 8) * PSTR + col + 1] = tf32r(p3);
        }
        ls0 += __shfl_xor_sync(0xffffffffu, ls0, 1);
        ls0 += __shfl_xor_sync(0xffffffffu, ls0, 2);
        ls1 += __shfl_xor_sync(0xffffffffu, ls1, 1);
        ls1 += __shfl_xor_sync(0xffffffffu, ls1, 2);
        l0 = l0 * a0 + ls0;
        l1 = l1 * a1 + ls1;
        m0 = mn0; m1 = mn1;
#pragma unroll
        for (int nt = 0; nt < 16; nt++) {
            o[nt][0] *= a0; o[nt][1] *= a0; o[nt][2] *= a1; o[nt][3] *= a1;
        }
        __syncwarp();

        const uint32_t* pu = reinterpret_cast<const uint32_t*>(Pw);
        const uint32_t* vu = reinterpret_cast<const uint32_t*>(Vs);
#pragma unroll
        for (int ks = 0; ks < 8; ks++) {
            const int k0 = ks * 8;
            uint32_t af[4] = {
                pu[g * PSTR + k0 + t],
                pu[(g + 8) * PSTR + k0 + t],
                pu[g * PSTR + k0 + t + 4],
                pu[(g + 8) * PSTR + k0 + t + 4] };
#pragma unroll
            for (int nt = 0; nt < 16; nt++) {
                uint32_t bf[2] = { vu[(k0 + t) * VSTR + nt * 8 + g],
                                   vu[(k0 + t + 4) * VSTR + nt * 8 + g] };
                mma8(o[nt], af, bf);
            }
        }
    }

    // permuted + rounded output store: within-8-block pos(j) = 2*(j%4) + j/4
    const float inv0 = 1.f / l0, inv1 = 1.f / l1;
    const int j0 = 2 * t, j1 = 2 * t + 1;
    const int p0 = 2 * (j0 & 3) + (j0 >> 2);
    const int p1 = 2 * (j1 & 3) + (j1 >> 2);
    float* op  = O + (rowbase + qbase + r0 + g) * MAT + h * HD;
    float* op2 = op + (size_t)8 * MAT;
#pragma unroll
    for (int nt = 0; nt < 16; nt++) {
        const int base = nt * 8;
        op [base + p0] = tf32r(o[nt][0] * inv0);
        op [base + p1] = tf32r(o[nt][1] * inv0);
        op2[base + p0] = tf32r(o[nt][2] * inv1);
        op2[base + p1] = tf32r(o[nt][3] * inv1);
    }
}

// ---------------------------------------------------------------------------
#define ATTN_SMEM ((128 * QSTR + 64 * KSTR + 64 * VSTR + 8 * 16 * PSTR) * 4)

extern "C" void kernel_launch(void* const* d_in, const int* in_sizes, int n_in,
                              void* d_out, int out_size)
{
    const float* x    = (const float*)d_in[0];
    const float* wq   = (const float*)d_in[1];
    const float* wk   = (const float*)d_in[2];
    const float* wv   = (const float*)d_in[3];
    const float* wo   = (const float*)d_in[4];
    const float* cosT = (const float*)d_in[5];
    const float* sinT = (const float*)d_in[6];
    float* out = (float*)d_out;

    cudaFuncSetAttribute(gemm_simt, cudaFuncAttributeMaxDynamicSharedMemorySize, GS);
    cudaFuncSetAttribute(attn128,  cudaFuncAttributeMaxDynamicSharedMemorySize, ATTN_SMEM);

    float *pq, *pk, *pv, *pa, *pxr, *pwq, *pwk, *pwv, *pwo;
    cudaGetSymbolAddress((void**)&pq,  g_q);
    cudaGetSymbolAddress((void**)&pk,  g_k);
    cudaGetSymbolAddress((void**)&pv,  g_v);
    cudaGetSymbolAddress((void**)&pa,  g_att);
    cudaGetSymbolAddress((void**)&pxr, g_xr);
    cudaGetSymbolAddress((void**)&pwq, g_wqr);
    cudaGetSymbolAddress((void**)&pwk, g_wkr);
    cudaGetSymbolAddress((void**)&pwv, g_wvr);
    cudaGetSymbolAddress((void**)&pwo, g_wor);

    const int n8 = (MAT * MAT) / 8;
    round_perm_k<<<2048, 256>>>((const float4*)x,  (float4*)pxr, n8);
    round_perm_k<<<2048, 256>>>((const float4*)wq, (float4*)pwq, n8);
    round_perm_k<<<2048, 256>>>((const float4*)wk, (float4*)pwk, n8);
    round_perm_k<<<2048, 256>>>((const float4*)wv, (float4*)pwv, n8);
    round_perm_k<<<2048, 256>>>((const float4*)wo, (float4*)pwo, n8);

    dim3 gg(MAT / BN, MAT / BM);   // (32, 32)
    gemm_simt<<<gg, 256, GS>>>(pxr, pwq, pq, cosT, sinT, 1);
    gemm_simt<<<gg, 256, GS>>>(pxr, pwk, pk, cosT, sinT, 1);
    gemm_simt<<<gg, 256, GS>>>(pxr, pwv, pv, cosT, sinT, 0);
    attn128<<<dim3(8, 32, 4), 256, ATTN_SMEM>>>(pq, pk, pv, pa);
    gemm_simt<<<gg, 256, GS>>>(pa, pwo, out, cosT, sinT, 0);
}

// round 7
// speedup vs baseline: 1.8229x; 1.8229x over previous
#include <cuda_runtime.h>
#include <cuda_fp16.h>
#include <cstdint>

#define MAT 4096
#define SQ  1024
#define HD  128
#define NEG_BIG (-1e30f)

// Scratch (allocation-free rule: device globals)
__device__ float  g_q  [(size_t)MAT * MAT];
__device__ float  g_k  [(size_t)MAT * MAT];
__device__ float  g_v  [(size_t)MAT * MAT];
__device__ __half g_att[(size_t)MAT * MAT];   // fp16, k-permuted
__device__ __half g_xh [(size_t)MAT * MAT];   // fp16, k-permuted
__device__ __half g_wqh[(size_t)MAT * MAT];
__device__ __half g_wkh[(size_t)MAT * MAT];
__device__ __half g_wvh[(size_t)MAT * MAT];
__device__ __half g_woh[(size_t)MAT * MAT];

// ---------------------------------------------------------------------------
__device__ __forceinline__ float tf32r(float x) {
    uint32_t u;
    asm("cvt.rna.tf32.f32 %0, %1;" : "=r"(u) : "f"(x));
    return __uint_as_float(u);
}

__device__ __forceinline__ uint32_t smem_u32(const void* p) {
    uint32_t a;
    asm("{ .reg .u64 t; cvta.to.shared.u64 t, %1; cvt.u32.u64 %0, t; }" : "=r"(a) : "l"(p));
    return a;
}

// tf32 m16n8k8 (attention kernel)
__device__ __forceinline__ void mma8(float c[4], const uint32_t a[4], const uint32_t b[2]) {
    asm volatile(
        "mma.sync.aligned.m16n8k8.row.col.f32.tf32.tf32.f32 "
        "{%0,%1,%2,%3},{%4,%5,%6,%7},{%8,%9},{%0,%1,%2,%3};\n"
        : "+f"(c[0]), "+f"(c[1]), "+f"(c[2]), "+f"(c[3])
        : "r"(a[0]), "r"(a[1]), "r"(a[2]), "r"(a[3]), "r"(b[0]), "r"(b[1]));
}

// fp16 m16n8k16, fp32 accumulate (GEMMs)
__device__ __forceinline__ void mma16(float c[4], const uint32_t a[4], const uint32_t b[2]) {
    asm volatile(
        "mma.sync.aligned.m16n8k16.row.col.f32.f16.f16.f32 "
        "{%0,%1,%2,%3},{%4,%5,%6,%7},{%8,%9},{%0,%1,%2,%3};\n"
        : "+f"(c[0]), "+f"(c[1]), "+f"(c[2]), "+f"(c[3])
        : "r"(a[0]), "r"(a[1]), "r"(a[2]), "r"(a[3]), "r"(b[0]), "r"(b[1]));
}

__device__ __forceinline__ void cpa16(uint32_t dst, const void* src) {
    asm volatile("cp.async.cg.shared.global [%0], [%1], 16;" :: "r"(dst), "l"(src));
}
#define CPA_COMMIT() asm volatile("cp.async.commit_group;" ::: "memory")
#define CPA_WAIT(n)  asm volatile("cp.async.wait_group %0;" :: "n"(n) : "memory")

// ---------------------------------------------------------------------------
// fp32 -> fp16 + k-permute pre-pass, all 5 matrices in one launch.
// Within each 16-element k-block, new position n holds old k(n):
//   t = n>>2, hi = (n>>1)&1, lo = n&1  ->  k = 2t + 8*hi + lo
// (so per-thread mma fragments become contiguous 8B runs).
// ---------------------------------------------------------------------------
__global__ void conv_h_perm(const float* __restrict__ i0, const float* __restrict__ i1,
                            const float* __restrict__ i2, const float* __restrict__ i3,
                            const float* __restrict__ i4,
                            __half* __restrict__ o0, __half* __restrict__ o1,
                            __half* __restrict__ o2, __half* __restrict__ o3,
                            __half* __restrict__ o4)
{
    const float* in;
    __half* out;
    switch (blockIdx.y) {
        case 0: in = i0; out = o0; break;
        case 1: in = i1; out = o1; break;
        case 2: in = i2; out = o2; break;
        case 3: in = i3; out = o3; break;
        default: in = i4; out = o4; break;
    }
    const int n16 = (MAT * MAT) / 16;
    int i = blockIdx.x * blockDim.x + threadIdx.x;
    const int stride = gridDim.x * blockDim.x;
    for (; i < n16; i += stride) {
        const float4* ip = reinterpret_cast<const float4*>(in) + 4 * (size_t)i;
        float v[16];
        *reinterpret_cast<float4*>(v)      = ip[0];
        *reinterpret_cast<float4*>(v + 4)  = ip[1];
        *reinterpret_cast<float4*>(v + 8)  = ip[2];
        *reinterpret_cast<float4*>(v + 12) = ip[3];
        __half h[16];
#pragma unroll
        for (int n = 0; n < 16; n++) {
            const int k = 2 * (n >> 2) + 8 * ((n >> 1) & 1) + (n & 1);
            h[n] = __float2half_rn(v[k]);
        }
        uint4* op = reinterpret_cast<uint4*>(out + 16 * (size_t)i);
        op[0] = *reinterpret_cast<uint4*>(h);
        op[1] = *reinterpret_cast<uint4*>(h + 8);
    }
}

// ---------------------------------------------------------------------------
// fp16 GEMM: C[m][n] = sum_k A[m][k]*W[n][k]  (4096^3), fp16 + k-permuted in.
// CTA 128x128, BK=64, 8 warps (warp tile 32x64), 2-stage cp.async pipeline.
// SSTRH=80 halves -> conflict-free LDS.64 fragments; 80KB smem -> 2 CTAs/SM.
// ---------------------------------------------------------------------------
#define BM 128
#define BN 128
#define BK 64
#define SSTRH 80                           // halves per row (160 B)
#define ABUFH (BM * SSTRH)                 // 10240 halves
#define SPFH  (2 * ABUFH)                  // halves per stage (A+B)
#define NSTG 2
#define GS   (NSTG * SPFH * 2)             // 81920 B
#define NKT  (MAT / BK)                    // 64

__global__ __launch_bounds__(256, 2) void gemm_h(
    const __half* __restrict__ A, const __half* __restrict__ W, float* __restrict__ C,
    const float* __restrict__ cosT, const float* __restrict__ sinT, int doRope)
{
    extern __shared__ __half smh[];
    const uint32_t smb = smem_u32(smh);

    const int tid = threadIdx.x;
    const int bn = blockIdx.x, bm = blockIdx.y;

    const __half* Abase = A + (size_t)(bm * BM) * MAT;
    const __half* Wbase = W + (size_t)(bn * BN) * MAT;

    auto issue = [&](int i) {
        const uint32_t as = smb + (uint32_t)((i & 1) * SPFH) * 2u;
        const uint32_t bs = as + ABUFH * 2u;
        const int kb = i * BK;
#pragma unroll
        for (int j = 0; j < 4; j++) {          // A: 1024 16B-chunks (128 rows x 128B)
            const int idx = tid + j * 256;
            const int r = idx >> 3, c = idx & 7;
            cpa16(as + (uint32_t)(r * SSTRH * 2 + c * 16),
                  Abase + (size_t)r * MAT + kb + c * 8);
        }
#pragma unroll
        for (int j = 0; j < 4; j++) {          // B: 1024 16B-chunks
            const int idx = tid + j * 256;
            const int r = idx >> 3, c = idx & 7;
            cpa16(bs + (uint32_t)(r * SSTRH * 2 + c * 16),
                  Wbase + (size_t)r * MAT + kb + c * 8);
        }
        CPA_COMMIT();
    };

    issue(0);
    issue(1);

    const int lane = tid & 31, wrp = tid >> 5;
    const int g = lane >> 2, t = lane & 3;
    const int m0 = (wrp & 3) * 32;            // 4 M-slots
    const int n0 = (wrp >> 2) * 64;           // 2 N-slots

    float acc[2][8][4];
#pragma unroll
    for (int a = 0; a < 2; a++)
#pragma unroll
        for (int b = 0; b < 8; b++)
#pragma unroll
            for (int c = 0; c < 4; c++) acc[a][b][c] = 0.f;

    for (int kt = 0; kt < NKT; kt++) {
        CPA_WAIT(1);
        __syncthreads();

        const uint2* s2 = reinterpret_cast<const uint2*>(smh + (kt & 1) * SPFH);
        const uint2* a2 = s2;                       // [r][SSTRH/4] in uint2 units
        const uint2* b2 = s2 + ABUFH / 4;

#pragma unroll
        for (int ks = 0; ks < 4; ks++) {            // 4 x k16 per BK=64
            const int kk = ks * 4 + t;              // uint2 col: (ks*16 + 4t)/4
            uint32_t af[2][4];
#pragma unroll
            for (int mt = 0; mt < 2; mt++) {
                const int r = m0 + mt * 16 + g;
                const uint2 lo = a2[r * (SSTRH / 4) + kk];        // (a0, a2)
                const uint2 hi = a2[(r + 8) * (SSTRH / 4) + kk];  // (a1, a3)
                af[mt][0] = lo.x; af[mt][1] = hi.x; af[mt][2] = lo.y; af[mt][3] = hi.y;
            }
#pragma unroll
            for (int nt = 0; nt < 8; nt++) {
                const int n = n0 + nt * 8 + g;
                const uint2 bb = b2[n * (SSTRH / 4) + kk];        // (b0, b1)
                uint32_t bf[2] = { bb.x, bb.y };
                mma16(acc[0][nt], af[0], bf);
                mma16(acc[1][nt], af[1], bf);
            }
        }

        if (kt + 2 < NKT) {
            __syncthreads();
            issue(kt + 2);
        }
    }

    // epilogue (+ fused RoPE); fp32 output, natural (non-permuted) layout
#pragma unroll
    for (int mt = 0; mt < 2; mt++) {
        const int gm = bm * BM + m0 + mt * 16 + g;
        const int s0 = gm & (SQ - 1);
#pragma unroll
        for (int nt = 0; nt < 8; nt++) {
            const int cloc = n0 + nt * 8 + 2 * t;       // < 128
            const int gn = bn * BN + cloc;
            float v0 = acc[mt][nt][0], v1 = acc[mt][nt][1];
            float v2 = acc[mt][nt][2], v3 = acc[mt][nt][3];
            if (doRope) {
                const int p = cloc >> 1;
                const float cc0 = cosT[s0 * 64 + p],       ss0 = sinT[s0 * 64 + p];
                const float cc1 = cosT[(s0 + 8) * 64 + p], ss1 = sinT[(s0 + 8) * 64 + p];
                const float w0 = v0 * cc0 - v1 * ss0;
                const float w1 = v0 * ss0 + v1 * cc0;
                const float w2 = v2 * cc1 - v3 * ss1;
                const float w3 = v2 * ss1 + v3 * cc1;
                v0 = w0; v1 = w1; v2 = w2; v3 = w3;
            }
            *reinterpret_cast<float2*>(C + (size_t)gm * MAT + gn)       = make_float2(v0, v1);
            *reinterpret_cast<float2*>(C + (size_t)(gm + 8) * MAT + gn) = make_float2(v2, v3);
        }
    }
}

// ---------------------------------------------------------------------------
// Flash attention (math unchanged). Epilogue stores fp16 + k-permuted so the
// Wo GEMM consumes it directly.
// ---------------------------------------------------------------------------
#define QSTR 132
#define KSTR 132
#define VSTR 136
#define PSTR 68

__global__ __launch_bounds__(256, 1) void attn128(
    const float* __restrict__ Q, const float* __restrict__ K,
    const float* __restrict__ V, __half* __restrict__ O)
{
    extern __shared__ float sm[];
    float* Qs = sm;
    float* Ks = Qs + 128 * QSTR;
    float* Vs = Ks + 64 * KSTR;
    float* Ps = Vs + 64 * VSTR;

    const int tid = threadIdx.x;
    const int qt = blockIdx.x, h = blockIdx.y, b = blockIdx.z;
    const int qbase = qt * 128;
    const size_t rowbase = (size_t)b * SQ;
    const float scale = 0.08838834764831845f;

    {
        const float* qp = Q + (rowbase + qbase) * MAT + h * HD;
#pragma unroll
        for (int i = 0; i < 16; i++) {
            int idx = tid + i * 256;
            int row = idx >> 5;
            int c4  = (idx & 31) << 2;
            float4 v = *reinterpret_cast<const float4*>(qp + (size_t)row * MAT + c4);
            v.x = tf32r(v.x * scale); v.y = tf32r(v.y * scale);
            v.z = tf32r(v.z * scale); v.w = tf32r(v.w * scale);
            *reinterpret_cast<float4*>(Qs + row * QSTR + c4) = v;
        }
    }

    const int lane = tid & 31, wrp = tid >> 5;
    const int g = lane >> 2, t = lane & 3;
    const int r0 = wrp * 16;

    float o[16][4];
#pragma unroll
    for (int i = 0; i < 16; i++)
#pragma unroll
        for (int j = 0; j < 4; j++) o[i][j] = 0.f;
    float m0 = NEG_BIG, m1 = NEG_BIG, l0 = 0.f, l1 = 0.f;

    const int nkt = 2 * qt + 2;
    for (int kt = 0; kt < nkt; kt++) {
        __syncthreads();
        {
            const float* kp = K + (rowbase + kt * 64) * MAT + h * HD;
            const float* vp = V + (rowbase + kt * 64) * MAT + h * HD;
#pragma unroll
            for (int i = 0; i < 8; i++) {
                int idx = tid + i * 256;
                int row = idx >> 5;
                int c4  = (idx & 31) << 2;
                float4 kv = *reinterpret_cast<const float4*>(kp + (size_t)row * MAT + c4);
                kv.x = tf32r(kv.x); kv.y = tf32r(kv.y); kv.z = tf32r(kv.z); kv.w = tf32r(kv.w);
                *reinterpret_cast<float4*>(Ks + row * KSTR + c4) = kv;
                float4 vv = *reinterpret_cast<const float4*>(vp + (size_t)row * MAT + c4);
                vv.x = tf32r(vv.x); vv.y = tf32r(vv.y); vv.z = tf32r(vv.z); vv.w = tf32r(vv.w);
                *reinterpret_cast<float4*>(Vs + row * VSTR + c4) = vv;
            }
        }
        __syncthreads();

        float sfr[8][4];
#pragma unroll
        for (int i = 0; i < 8; i++)
#pragma unroll
            for (int j = 0; j < 4; j++) sfr[i][j] = 0.f;

        const uint32_t* qsu = reinterpret_cast<const uint32_t*>(Qs);
        const uint32_t* ksu = reinterpret_cast<const uint32_t*>(Ks);
#pragma unroll
        for (int ks = 0; ks < 16; ks++) {
            const int k0 = ks * 8;
            uint32_t af[4] = {
                qsu[(r0 + g) * QSTR + k0 + t],
                qsu[(r0 + g + 8) * QSTR + k0 + t],
                qsu[(r0 + g) * QSTR + k0 + t + 4],
                qsu[(r0 + g + 8) * QSTR + k0 + t + 4] };
#pragma unroll
            for (int nt = 0; nt < 8; nt++) {
                uint32_t bf[2] = { ksu[(nt * 8 + g) * KSTR + k0 + t],
                                   ksu[(nt * 8 + g) * KSTR + k0 + t + 4] };
                mma8(sfr[nt], af, bf);
            }
        }

        if (kt >= 2 * qt) {
            const int qg0 = qbase + r0 + g;
            const int qg1 = qg0 + 8;
#pragma unroll
            for (int nt = 0; nt < 8; nt++) {
                const int kg = kt * 64 + nt * 8 + 2 * t;
                if (kg     > qg0) sfr[nt][0] = NEG_BIG;
                if (kg + 1 > qg0) sfr[nt][1] = NEG_BIG;
                if (kg     > qg1) sfr[nt][2] = NEG_BIG;
                if (kg + 1 > qg1) sfr[nt][3] = NEG_BIG;
            }
        }

        float tm0 = NEG_BIG, tm1 = NEG_BIG;
#pragma unroll
        for (int nt = 0; nt < 8; nt++) {
            tm0 = fmaxf(tm0, fmaxf(sfr[nt][0], sfr[nt][1]));
            tm1 = fmaxf(tm1, fmaxf(sfr[nt][2], sfr[nt][3]));
        }
        tm0 = fmaxf(tm0, __shfl_xor_sync(0xffffffffu, tm0, 1));
        tm0 = fmaxf(tm0, __shfl_xor_sync(0xffffffffu, tm0, 2));
        tm1 = fmaxf(tm1, __shfl_xor_sync(0xffffffffu, tm1, 1));
        tm1 = fmaxf(tm1, __shfl_xor_sync(0xffffffffu, tm1, 2));

        const float mn0 = fmaxf(m0, tm0), mn1 = fmaxf(m1, tm1);
        const float a0 = __expf(m0 - mn0), a1 = __expf(m1 - mn1);
        float ls0 = 0.f, ls1 = 0.f;
        float* Pw = Ps + wrp * 16 * PSTR;
#pragma unroll
        for (int nt = 0; nt < 8; nt++) {
            const int col = nt * 8 + 2 * t;
            float p0 = __expf(sfr[nt][0] - mn0);
            float p1 = __expf(sfr[nt][1] - mn0);
            float p2 = __expf(sfr[nt][2] - mn1);
            float p3 = __expf(sfr[nt][3] - mn1);
            ls0 += p0 + p1; ls1 += p2 + p3;
            Pw[g * PSTR + col]           = tf32r(p0);
            Pw[g * PSTR + col + 1]       = tf32r(p1);
            Pw[(g + 8) * PSTR + col]     = tf32r(p2);
            Pw[(g + 8) * PSTR + col + 1] = tf32r(p3);
        }
        ls0 += __shfl_xor_sync(0xffffffffu, ls0, 1);
        ls0 += __shfl_xor_sync(0xffffffffu, ls0, 2);
        ls1 += __shfl_xor_sync(0xffffffffu, ls1, 1);
        ls1 += __shfl_xor_sync(0xffffffffu, ls1, 2);
        l0 = l0 * a0 + ls0;
        l1 = l1 * a1 + ls1;
        m0 = mn0; m1 = mn1;
#pragma unroll
        for (int nt = 0; nt < 16; nt++) {
            o[nt][0] *= a0; o[nt][1] *= a0; o[nt][2] *= a1; o[nt][3] *= a1;
        }
        __syncwarp();

        const uint32_t* pu = reinterpret_cast<const uint32_t*>(Pw);
        const uint32_t* vu = reinterpret_cast<const uint32_t*>(Vs);
#pragma unroll
        for (int ks = 0; ks < 8; ks++) {
            const int k0 = ks * 8;
            uint32_t af[4] = {
                pu[g * PSTR + k0 + t],
                pu[(g + 8) * PSTR + k0 + t],
                pu[g * PSTR + k0 + t + 4],
                pu[(g + 8) * PSTR + k0 + t + 4] };
#pragma unroll
            for (int nt = 0; nt < 16; nt++) {
                uint32_t bf[2] = { vu[(k0 + t) * VSTR + nt * 8 + g],
                                   vu[(k0 + t + 4) * VSTR + nt * 8 + g] };
                mma8(o[nt], af, bf);
            }
        }
    }

    // fp16 + k-permuted output store.
    // Global col k = nt*8 + 2t (+1). Within its 16-block, the permuted
    // position of the pair is 4t + 2*(nt&1) (+1)  -> adjacent half2.
    const float inv0 = 1.f / l0, inv1 = 1.f / l1;
    const int poff = 4 * t + 2 * (lane & 0);  // placeholder avoids warnings
    (void)poff;
    __half* op  = O + (rowbase + qbase + r0 + g) * MAT + h * HD;
    __half* op2 = op + (size_t)8 * MAT;
#pragma unroll
    for (int nt = 0; nt < 16; nt++) {
        const int pos = (nt >> 1) * 16 + 4 * t + 2 * (nt & 1);
        __half2 h0 = __floats2half2_rn(o[nt][0] * inv0, o[nt][1] * inv0);
        __half2 h1 = __floats2half2_rn(o[nt][2] * inv1, o[nt][3] * inv1);
        *reinterpret_cast<__half2*>(op  + pos) = h0;
        *reinterpret_cast<__half2*>(op2 + pos) = h1;
    }
}

// ---------------------------------------------------------------------------
#define ATTN_SMEM ((128 * QSTR + 64 * KSTR + 64 * VSTR + 8 * 16 * PSTR) * 4)

extern "C" void kernel_launch(void* const* d_in, const int* in_sizes, int n_in,
                              void* d_out, int out_size)
{
    const float* x    = (const float*)d_in[0];
    const float* wq   = (const float*)d_in[1];
    const float* wk   = (const float*)d_in[2];
    const float* wv   = (const float*)d_in[3];
    const float* wo   = (const float*)d_in[4];
    const float* cosT = (const float*)d_in[5];
    const float* sinT = (const float*)d_in[6];
    float* out = (float*)d_out;

    cudaFuncSetAttribute(gemm_h,  cudaFuncAttributeMaxDynamicSharedMemorySize, GS);
    cudaFuncSetAttribute(attn128, cudaFuncAttributeMaxDynamicSharedMemorySize, ATTN_SMEM);

    float  *pq, *pk, *pv;
    __half *pa, *pxh, *pwq, *pwk, *pwv, *pwo;
    cudaGetSymbolAddress((void**)&pq,  g_q);
    cudaGetSymbolAddress((void**)&pk,  g_k);
    cudaGetSymbolAddress((void**)&pv,  g_v);
    cudaGetSymbolAddress((void**)&pa,  g_att);
    cudaGetSymbolAddress((void**)&pxh, g_xh);
    cudaGetSymbolAddress((void**)&pwq, g_wqh);
    cudaGetSymbolAddress((void**)&pwk, g_wkh);
    cudaGetSymbolAddress((void**)&pwv, g_wvh);
    cudaGetSymbolAddress((void**)&pwo, g_woh);

    // launch 0: fused fp16 conversion (all 5 matrices)
    conv_h_perm<<<dim3(1024, 5), 256>>>(x, wq, wk, wv, wo, pxh, pwq, pwk, pwv, pwo);

    dim3 gg(MAT / BN, MAT / BM);   // (32, 32)
    gemm_h<<<gg, 256, GS>>>(pxh, pwq, pq, cosT, sinT, 1);   // launch 1
    gemm_h<<<gg, 256, GS>>>(pxh, pwk, pk, cosT, sinT, 1);   // launch 2
    gemm_h<<<gg, 256, GS>>>(pxh, pwv, pv, cosT, sinT, 0);   // launch 3
    attn128<<<dim3(8, 32, 4), 256, ATTN_SMEM>>>(pq, pk, pv, pa);  // launch 4
    gemm_h<<<gg, 256, GS>>>(pa, pwo, out, cosT, sinT, 0);   // launch 5 (ncu -s 5)
}

// round 8
// speedup vs baseline: 1.9088x; 1.0471x over previous
#include <cuda_runtime.h>
#include <cuda_fp16.h>
#include <cstdint>

#define MAT 4096
#define SQ  1024
#define HD  128
#define NEG_BIG (-1e30f)

// Scratch (allocation-free rule: device globals)
__device__ __half g_qh [(size_t)MAT * MAT];   // Q fp16, roped+scaled, natural
__device__ __half g_kh [(size_t)MAT * MAT];   // K fp16, roped, natural
__device__ __half g_vh [(size_t)MAT * MAT];   // V fp16, natural
__device__ __half g_vt [(size_t)MAT * MAT];   // V^T fp16  [h*128+d][b*1024+s]
__device__ __half g_att[(size_t)MAT * MAT];   // attn out fp16, k-permuted
__device__ __half g_xh [(size_t)MAT * MAT];   // x fp16, k-permuted
__device__ __half g_wqh[(size_t)MAT * MAT];
__device__ __half g_wkh[(size_t)MAT * MAT];
__device__ __half g_wvh[(size_t)MAT * MAT];
__device__ __half g_woh[(size_t)MAT * MAT];

// ---------------------------------------------------------------------------
__device__ __forceinline__ uint32_t smem_u32(const void* p) {
    uint32_t a;
    asm("{ .reg .u64 t; cvta.to.shared.u64 t, %1; cvt.u32.u64 %0, t; }" : "=r"(a) : "l"(p));
    return a;
}

// fp16 m16n8k16, fp32 accumulate
__device__ __forceinline__ void mma16(float c[4], const uint32_t a[4], const uint32_t b[2]) {
    asm volatile(
        "mma.sync.aligned.m16n8k16.row.col.f32.f16.f16.f32 "
        "{%0,%1,%2,%3},{%4,%5,%6,%7},{%8,%9},{%0,%1,%2,%3};\n"
        : "+f"(c[0]), "+f"(c[1]), "+f"(c[2]), "+f"(c[3])
        : "r"(a[0]), "r"(a[1]), "r"(a[2]), "r"(a[3]), "r"(b[0]), "r"(b[1]));
}

__device__ __forceinline__ void lds64(uint32_t& x, uint32_t& y, uint32_t addr) {
    asm volatile("ld.shared.v2.b32 {%0,%1}, [%2];" : "=r"(x), "=r"(y) : "r"(addr));
}

__device__ __forceinline__ void cpa16(uint32_t dst, const void* src) {
    asm volatile("cp.async.cg.shared.global [%0], [%1], 16;" :: "r"(dst), "l"(src));
}
#define CPA_COMMIT() asm volatile("cp.async.commit_group;" ::: "memory")
#define CPA_WAIT(n)  asm volatile("cp.async.wait_group %0;" :: "n"(n) : "memory")

// ---------------------------------------------------------------------------
// fp32 -> fp16 + k-permute pre-pass (GEMM operand layout), 5 matrices.
// Within each 16-block, new position n holds old k = 2*(n>>2) + 8*((n>>1)&1) + (n&1).
// ---------------------------------------------------------------------------
__global__ void conv_h_perm(const float* __restrict__ i0, const float* __restrict__ i1,
                            const float* __restrict__ i2, const float* __restrict__ i3,
                            const float* __restrict__ i4,
                            __half* __restrict__ o0, __half* __restrict__ o1,
                            __half* __restrict__ o2, __half* __restrict__ o3,
                            __half* __restrict__ o4)
{
    const float* in;
    __half* out;
    switch (blockIdx.y) {
        case 0: in = i0; out = o0; break;
        case 1: in = i1; out = o1; break;
        case 2: in = i2; out = o2; break;
        case 3: in = i3; out = o3; break;
        default: in = i4; out = o4; break;
    }
    const int n16 = (MAT * MAT) / 16;
    int i = blockIdx.x * blockDim.x + threadIdx.x;
    const int stride = gridDim.x * blockDim.x;
    for (; i < n16; i += stride) {
        const float4* ip = reinterpret_cast<const float4*>(in) + 4 * (size_t)i;
        float v[16];
        *reinterpret_cast<float4*>(v)      = ip[0];
        *reinterpret_cast<float4*>(v + 4)  = ip[1];
        *reinterpret_cast<float4*>(v + 8)  = ip[2];
        *reinterpret_cast<float4*>(v + 12) = ip[3];
        __half h[16];
#pragma unroll
        for (int n = 0; n < 16; n++) {
            const int k = 2 * (n >> 2) + 8 * ((n >> 1) & 1) + (n & 1);
            h[n] = __float2half_rn(v[k]);
        }
        uint4* op = reinterpret_cast<uint4*>(out + 16 * (size_t)i);
        op[0] = *reinterpret_cast<uint4*>(h);
        op[1] = *reinterpret_cast<uint4*>(h + 8);
    }
}

// ---------------------------------------------------------------------------
// fp16 GEMM: C[m][n] = sum_k A[m][k]*W[n][k]  (4096^3), fp16 + k-permuted in.
// CTA 128x128, BK=64, 8 warps (warp tile 32x64), 2-stage cp.async pipeline.
// Flat-u32 smem addressing -> fragment LDS.64 with immediate offsets.
// Epilogue: f32 natural OR f16 natural (+RoPE, +scale).
// ---------------------------------------------------------------------------
#define BM 128
#define BN 128
#define BK 64
#define SSTRH 80                           // halves per row (160 B)
#define ABUFH (BM * SSTRH)                 // 10240 halves
#define SPFH  (2 * ABUFH)
#define GS    (2 * SPFH * 2)               // 81920 B
#define NKT   (MAT / BK)                   // 64

__global__ __launch_bounds__(256, 2) void gemm_h(
    const __half* __restrict__ A, const __half* __restrict__ W, void* __restrict__ Cv,
    const float* __restrict__ cosT, const float* __restrict__ sinT,
    int doRope, int f16out, float oscale)
{
    extern __shared__ __half smh[];
    const uint32_t smb = smem_u32(smh);

    const int tid = threadIdx.x;
    const int bn = blockIdx.x, bm = blockIdx.y;

    const __half* Abase = A + (size_t)(bm * BM) * MAT;
    const __half* Wbase = W + (size_t)(bn * BN) * MAT;

    auto issue = [&](int i) {
        const uint32_t as = smb + (uint32_t)(i & 1) * (SPFH * 2);
        const uint32_t bs = as + ABUFH * 2u;
        const int kb = i * BK;
#pragma unroll
        for (int j = 0; j < 4; j++) {
            const int idx = tid + j * 256;
            const int r = idx >> 3, c = idx & 7;
            cpa16(as + (uint32_t)(r * 160 + c * 16), Abase + (size_t)r * MAT + kb + c * 8);
        }
#pragma unroll
        for (int j = 0; j < 4; j++) {
            const int idx = tid + j * 256;
            const int r = idx >> 3, c = idx & 7;
            cpa16(bs + (uint32_t)(r * 160 + c * 16), Wbase + (size_t)r * MAT + kb + c * 8);
        }
        CPA_COMMIT();
    };

    issue(0);
    issue(1);

    const int lane = tid & 31, wrp = tid >> 5;
    const int g = lane >> 2, t = lane & 3;
    const int m0 = (wrp & 3) * 32;            // 4 M-slots
    const int n0 = (wrp >> 2) * 64;           // 2 N-slots

    // flat smem base addresses (bytes): fragment = base + const
    const uint32_t aB0 = smb + (uint32_t)(m0 + g) * 160u + (uint32_t)t * 8u;
    const uint32_t bB0 = smb + ABUFH * 2u + (uint32_t)(n0 + g) * 160u + (uint32_t)t * 8u;

    float acc[2][8][4];
#pragma unroll
    for (int a = 0; a < 2; a++)
#pragma unroll
        for (int b = 0; b < 8; b++)
#pragma unroll
            for (int c = 0; c < 4; c++) acc[a][b][c] = 0.f;

    for (int kt = 0; kt < NKT; kt++) {
        CPA_WAIT(1);
        __syncthreads();

        const uint32_t sel = (uint32_t)(kt & 1) * (SPFH * 2);
        const uint32_t aB = aB0 + sel;
        const uint32_t bB = bB0 + sel;

#pragma unroll
        for (int ks = 0; ks < 4; ks++) {
            uint32_t af[2][4];
#pragma unroll
            for (int mt = 0; mt < 2; mt++) {
                lds64(af[mt][0], af[mt][2], aB + mt * 2560 + ks * 32);
                lds64(af[mt][1], af[mt][3], aB + mt * 2560 + 1280 + ks * 32);
            }
#pragma unroll
            for (int nt = 0; nt < 8; nt++) {
                uint32_t bf[2];
                lds64(bf[0], bf[1], bB + nt * 1280 + ks * 32);
                mma16(acc[0][nt], af[0], bf);
                mma16(acc[1][nt], af[1], bf);
            }
        }

        if (kt + 2 < NKT) {
            __syncthreads();
            issue(kt + 2);
        }
    }

    // epilogue (+ fused RoPE); natural layout
#pragma unroll
    for (int mt = 0; mt < 2; mt++) {
        const int gm = bm * BM + m0 + mt * 16 + g;
        const int s0 = gm & (SQ - 1);
#pragma unroll
        for (int nt = 0; nt < 8; nt++) {
            const int cloc = n0 + nt * 8 + 2 * t;       // < 128
            const int gn = bn * BN + cloc;
            float v0 = acc[mt][nt][0], v1 = acc[mt][nt][1];
            float v2 = acc[mt][nt][2], v3 = acc[mt][nt][3];
            if (doRope) {
                const int p = cloc >> 1;
                const float cc0 = cosT[s0 * 64 + p],       ss0 = sinT[s0 * 64 + p];
                const float cc1 = cosT[(s0 + 8) * 64 + p], ss1 = sinT[(s0 + 8) * 64 + p];
                const float w0 = v0 * cc0 - v1 * ss0;
                const float w1 = v0 * ss0 + v1 * cc0;
                const float w2 = v2 * cc1 - v3 * ss1;
                const float w3 = v2 * ss1 + v3 * cc1;
                v0 = w0; v1 = w1; v2 = w2; v3 = w3;
            }
            if (f16out) {
                __half* Ch = (__half*)Cv;
                *reinterpret_cast<__half2*>(Ch + (size_t)gm * MAT + gn) =
                    __floats2half2_rn(v0 * oscale, v1 * oscale);
                *reinterpret_cast<__half2*>(Ch + (size_t)(gm + 8) * MAT + gn) =
                    __floats2half2_rn(v2 * oscale, v3 * oscale);
            } else {
                float* Cf = (float*)Cv;
                *reinterpret_cast<float2*>(Cf + (size_t)gm * MAT + gn)       = make_float2(v0, v1);
                *reinterpret_cast<float2*>(Cf + (size_t)(gm + 8) * MAT + gn) = make_float2(v2, v3);
            }
        }
    }
}

// ---------------------------------------------------------------------------
// Tiled fp16 transpose: out[c][r] = in[r][c]  (4096x4096)
// ---------------------------------------------------------------------------
__global__ __launch_bounds__(256, 4) void transpose_h(
    const __half* __restrict__ in, __half* __restrict__ out)
{
    __shared__ __half ts[64][72];
    const int tid = threadIdx.x;
    const int bx = blockIdx.x, by = blockIdx.y;   // by: in-row tile, bx: in-col tile
#pragma unroll
    for (int i = 0; i < 2; i++) {
        const int idx = tid + i * 256;
        const int r = idx >> 3, c = idx & 7;
        *reinterpret_cast<uint4*>(&ts[r][c * 8]) =
            *reinterpret_cast<const uint4*>(in + (size_t)(by * 64 + r) * MAT + bx * 64 + c * 8);
    }
    __syncthreads();
#pragma unroll
    for (int i = 0; i < 2; i++) {
        const int idx = tid + i * 256;
        const int r = idx >> 3, c = idx & 7;     // r = out-row within tile (= in col)
        __half tmp[8];
#pragma unroll
        for (int j = 0; j < 8; j++) tmp[j] = ts[c * 8 + j][r];
        *reinterpret_cast<uint4*>(out + (size_t)(bx * 64 + r) * MAT + by * 64 + c * 8) =
            *reinterpret_cast<uint4*>(tmp);
    }
}

// ---------------------------------------------------------------------------
// Flash attention, fp16 mma16. Inputs: Q (scaled+roped fp16), K (roped fp16),
// V^T fp16. Output fp16 k-permuted for Wo GEMM.
// Smem (dwords): Q[128][68] K[64][68] V[128][36] P[8][16][36]
// ---------------------------------------------------------------------------
#define AQSTR 68
#define AVSTR 36
#define ATTN_DW (128 * AQSTR + 64 * AQSTR + 128 * AVSTR + 8 * 16 * AVSTR)
#define ATTN_SMEM (ATTN_DW * 4)

__global__ __launch_bounds__(256, 1) void attn_h(
    const __half* __restrict__ Q, const __half* __restrict__ K,
    const __half* __restrict__ VT, __half* __restrict__ O)
{
    extern __shared__ uint32_t asmem[];
    uint32_t* Qd = asmem;
    uint32_t* Kd = Qd + 128 * AQSTR;
    uint32_t* Vd = Kd + 64 * AQSTR;
    uint32_t* Pd = Vd + 128 * AVSTR;

    const int tid = threadIdx.x;
    const int qt = blockIdx.x, h = blockIdx.y, b = blockIdx.z;
    const int qbase = qt * 128;
    const size_t rowbase = (size_t)b * SQ;

    {   // load Q tile (fp16, already scaled + roped)
        const __half* qp = Q + (rowbase + qbase) * MAT + h * HD;
#pragma unroll
        for (int i = 0; i < 8; i++) {
            const int idx = tid + i * 256;
            const int row = idx >> 4, c = idx & 15;
            *reinterpret_cast<uint4*>(Qd + row * AQSTR + c * 4) =
                *reinterpret_cast<const uint4*>(qp + (size_t)row * MAT + c * 8);
        }
    }

    const int lane = tid & 31, wrp = tid >> 5;
    const int g = lane >> 2, t = lane & 3;
    const int r0 = wrp * 16;
    uint32_t* Pw = Pd + wrp * 16 * AVSTR;

    float o[16][4];
#pragma unroll
    for (int i = 0; i < 16; i++)
#pragma unroll
        for (int j = 0; j < 4; j++) o[i][j] = 0.f;
    float m0 = NEG_BIG, m1 = NEG_BIG, l0 = 0.f, l1 = 0.f;

    const int nkt = 2 * qt + 2;
    for (int kt = 0; kt < nkt; kt++) {
        __syncthreads();
        {
            const __half* kp = K + (rowbase + kt * 64) * MAT + h * HD;
            const __half* vp = VT + (size_t)(h * HD) * MAT + b * SQ + kt * 64;
#pragma unroll
            for (int i = 0; i < 4; i++) {
                const int idx = tid + i * 256;
                const int row = idx >> 4, c = idx & 15;
                *reinterpret_cast<uint4*>(Kd + row * AQSTR + c * 4) =
                    *reinterpret_cast<const uint4*>(kp + (size_t)row * MAT + c * 8);
            }
#pragma unroll
            for (int i = 0; i < 4; i++) {
                const int idx = tid + i * 256;
                const int row = idx >> 3, c = idx & 7;
                *reinterpret_cast<uint4*>(Vd + row * AVSTR + c * 4) =
                    *reinterpret_cast<const uint4*>(vp + (size_t)row * MAT + c * 8);
            }
        }
        __syncthreads();

        // S = Q K^T : 8 k16 steps over d=128, 8 key-tiles of 8
        float sfr[8][4];
#pragma unroll
        for (int i = 0; i < 8; i++)
#pragma unroll
            for (int j = 0; j < 4; j++) sfr[i][j] = 0.f;

#pragma unroll
        for (int ks = 0; ks < 8; ks++) {
            const int kd = ks * 8 + t;
            uint32_t af[4] = {
                Qd[(r0 + g) * AQSTR + kd],
                Qd[(r0 + g + 8) * AQSTR + kd],
                Qd[(r0 + g) * AQSTR + kd + 4],
                Qd[(r0 + g + 8) * AQSTR + kd + 4] };
#pragma unroll
            for (int nt = 0; nt < 8; nt++) {
                uint32_t bf[2] = { Kd[(nt * 8 + g) * AQSTR + kd],
                                   Kd[(nt * 8 + g) * AQSTR + kd + 4] };
                mma16(sfr[nt], af, bf);
            }
        }

        if (kt >= 2 * qt) {   // diagonal tiles: causal mask
            const int qg0 = qbase + r0 + g;
            const int qg1 = qg0 + 8;
#pragma unroll
            for (int nt = 0; nt < 8; nt++) {
                const int kg = kt * 64 + nt * 8 + 2 * t;
                if (kg     > qg0) sfr[nt][0] = NEG_BIG;
                if (kg + 1 > qg0) sfr[nt][1] = NEG_BIG;
                if (kg     > qg1) sfr[nt][2] = NEG_BIG;
                if (kg + 1 > qg1) sfr[nt][3] = NEG_BIG;
            }
        }

        // online softmax
        float tm0 = NEG_BIG, tm1 = NEG_BIG;
#pragma unroll
        for (int nt = 0; nt < 8; nt++) {
            tm0 = fmaxf(tm0, fmaxf(sfr[nt][0], sfr[nt][1]));
            tm1 = fmaxf(tm1, fmaxf(sfr[nt][2], sfr[nt][3]));
        }
        tm0 = fmaxf(tm0, __shfl_xor_sync(0xffffffffu, tm0, 1));
        tm0 = fmaxf(tm0, __shfl_xor_sync(0xffffffffu, tm0, 2));
        tm1 = fmaxf(tm1, __shfl_xor_sync(0xffffffffu, tm1, 1));
        tm1 = fmaxf(tm1, __shfl_xor_sync(0xffffffffu, tm1, 2));

        const float mn0 = fmaxf(m0, tm0), mn1 = fmaxf(m1, tm1);
        const float a0 = __expf(m0 - mn0), a1 = __expf(m1 - mn1);
        float ls0 = 0.f, ls1 = 0.f;
#pragma unroll
        for (int nt = 0; nt < 8; nt++) {
            float p0 = __expf(sfr[nt][0] - mn0);
            float p1 = __expf(sfr[nt][1] - mn0);
            float p2 = __expf(sfr[nt][2] - mn1);
            float p3 = __expf(sfr[nt][3] - mn1);
            ls0 += p0 + p1; ls1 += p2 + p3;
            __half2 h01 = __floats2half2_rn(p0, p1);
            __half2 h23 = __floats2half2_rn(p2, p3);
            Pw[g * AVSTR + nt * 4 + t]       = *reinterpret_cast<uint32_t*>(&h01);
            Pw[(g + 8) * AVSTR + nt * 4 + t] = *reinterpret_cast<uint32_t*>(&h23);
        }
        ls0 += __shfl_xor_sync(0xffffffffu, ls0, 1);
        ls0 += __shfl_xor_sync(0xffffffffu, ls0, 2);
        ls1 += __shfl_xor_sync(0xffffffffu, ls1, 1);
        ls1 += __shfl_xor_sync(0xffffffffu, ls1, 2);
        l0 = l0 * a0 + ls0;
        l1 = l1 * a1 + ls1;
        m0 = mn0; m1 = mn1;
#pragma unroll
        for (int nt = 0; nt < 16; nt++) {
            o[nt][0] *= a0; o[nt][1] *= a0; o[nt][2] *= a1; o[nt][3] *= a1;
        }
        __syncwarp();

        // O += P V : 4 k16 steps over seq 64, 16 d-tiles of 8
#pragma unroll
        for (int ks = 0; ks < 4; ks++) {
            const int kd = ks * 8 + t;
            uint32_t af[4] = {
                Pw[g * AVSTR + kd],
                Pw[(g + 8) * AVSTR + kd],
                Pw[g * AVSTR + kd + 4],
                Pw[(g + 8) * AVSTR + kd + 4] };
#pragma unroll
            for (int nt = 0; nt < 16; nt++) {
                uint32_t bf[2] = { Vd[(nt * 8 + g) * AVSTR + kd],
                                   Vd[(nt * 8 + g) * AVSTR + kd + 4] };
                mma16(o[nt], af, bf);
            }
        }
    }

    // fp16 + k-permuted output store (Wo GEMM operand layout)
    const float inv0 = 1.f / l0, inv1 = 1.f / l1;
    __half* op  = O + (rowbase + qbase + r0 + g) * MAT + h * HD;
    __half* op2 = op + (size_t)8 * MAT;
#pragma unroll
    for (int nt = 0; nt < 16; nt++) {
        const int pos = (nt >> 1) * 16 + 4 * t + 2 * (nt & 1);
        __half2 h0 = __floats2half2_rn(o[nt][0] * inv0, o[nt][1] * inv0);
        __half2 h1 = __floats2half2_rn(o[nt][2] * inv1, o[nt][3] * inv1);
        *reinterpret_cast<__half2*>(op  + pos) = h0;
        *reinterpret_cast<__half2*>(op2 + pos) = h1;
    }
}

// ---------------------------------------------------------------------------
extern "C" void kernel_launch(void* const* d_in, const int* in_sizes, int n_in,
                              void* d_out, int out_size)
{
    const float* x    = (const float*)d_in[0];
    const float* wq   = (const float*)d_in[1];
    const float* wk   = (const float*)d_in[2];
    const float* wv   = (const float*)d_in[3];
    const float* wo   = (const float*)d_in[4];
    const float* cosT = (const float*)d_in[5];
    const float* sinT = (const float*)d_in[6];
    float* out = (float*)d_out;

    cudaFuncSetAttribute(gemm_h, cudaFuncAttributeMaxDynamicSharedMemorySize, GS);
    cudaFuncSetAttribute(attn_h, cudaFuncAttributeMaxDynamicSharedMemorySize, ATTN_SMEM);

    __half *pq, *pk, *pv, *pvt, *pa, *pxh, *pwq, *pwk, *pwv, *pwo;
    cudaGetSymbolAddress((void**)&pq,  g_qh);
    cudaGetSymbolAddress((void**)&pk,  g_kh);
    cudaGetSymbolAddress((void**)&pv,  g_vh);
    cudaGetSymbolAddress((void**)&pvt, g_vt);
    cudaGetSymbolAddress((void**)&pa,  g_att);
    cudaGetSymbolAddress((void**)&pxh, g_xh);
    cudaGetSymbolAddress((void**)&pwq, g_wqh);
    cudaGetSymbolAddress((void**)&pwk, g_wkh);
    cudaGetSymbolAddress((void**)&pwv, g_wvh);
    cudaGetSymbolAddress((void**)&pwo, g_woh);

    conv_h_perm<<<dim3(1024, 5), 256>>>(x, wq, wk, wv, wo, pxh, pwq, pwk, pwv, pwo);

    dim3 gg(MAT / BN, MAT / BM);   // (32, 32)
    const float qs = 0.08838834764831845f;   // 1/sqrt(128)
    gemm_h<<<gg, 256, GS>>>(pxh, pwq, pq, cosT, sinT, 1, 1, qs);
    gemm_h<<<gg, 256, GS>>>(pxh, pwk, pk, cosT, sinT, 1, 1, 1.0f);
    gemm_h<<<gg, 256, GS>>>(pxh, pwv, pv, cosT, sinT, 0, 1, 1.0f);
    transpose_h<<<dim3(64, 64), 256>>>(pv, pvt);
    attn_h<<<dim3(8, 32, 4), 256, ATTN_SMEM>>>(pq, pk, pvt, pa);
    gemm_h<<<gg, 256, GS>>>(pa, pwo, out, cosT, sinT, 0, 0, 1.0f);
}